// round 7
// baseline (speedup 1.0000x reference)
#include <cuda_runtime.h>
#include <math.h>
#include <stdint.h>

// Problem constants
#define N_B     32
#define C_DIM   384
#define HW      3136        // 56*56
#define M_DIM   8
#define D_MODEL 768
#define E_DIM   768         // 2*C
#define KV_N    (M_DIM * E_DIM)   // 6144 per batch

// ---------------- device scratch -----------------------------------------------
__device__ __align__(16) float g_kv[N_B * KV_N];   // clipped KV [n][m][e]

// ================= Kernel 1: direct KV = clip(gf @ W^T + b) ====================
// grid (12, 32): CTA = (64-e block, batch). 256 thr: m = tid>>5, lane el -> 2 e.
__global__ __launch_bounds__(256) void kv_kernel(
    const float* __restrict__ gf,
    const float* __restrict__ W,
    const float* __restrict__ bias)
{
    __shared__ float gs[M_DIM * D_MODEL];   // 24 KB, gf for this batch

    const int tid = threadIdx.x;
    const int eb  = blockIdx.x * 64;
    const int n   = blockIdx.y;

    {   // stage gf[n] (1536 float4, coalesced)
        const float4* g4 = (const float4*)(gf + (size_t)n * (M_DIM * D_MODEL));
        #pragma unroll
        for (int t = 0; t < 6; t++) ((float4*)gs)[tid + t * 256] = g4[tid + t * 256];
    }
    __syncthreads();

    const int m  = tid >> 5;
    const int el = tid & 31;
    const int e0 = eb + el;
    const int e1 = eb + 32 + el;
    const float4* w0 = (const float4*)(W + (size_t)e0 * D_MODEL);
    const float4* w1 = (const float4*)(W + (size_t)e1 * D_MODEL);
    const float4* gm = (const float4*)(gs + m * D_MODEL);

    float4 a0 = make_float4(0.f, 0.f, 0.f, 0.f);
    float4 a1 = make_float4(0.f, 0.f, 0.f, 0.f);
    #pragma unroll 8
    for (int d = 0; d < D_MODEL / 4; d++) {
        float4 g  = gm[d];                 // warp-broadcast (same m)
        float4 x0 = __ldg(&w0[d]);
        float4 x1 = __ldg(&w1[d]);
        a0.x += g.x * x0.x; a0.y += g.y * x0.y; a0.z += g.z * x0.z; a0.w += g.w * x0.w;
        a1.x += g.x * x1.x; a1.y += g.y * x1.y; a1.z += g.z * x1.z; a1.w += g.w * x1.w;
    }
    float r0 = a0.x + a0.y + a0.z + a0.w + bias[e0];
    float r1 = a1.x + a1.y + a1.z + a1.w + bias[e1];
    r0 = fminf(fmaxf(r0, 0.f), 6.f);
    r1 = fminf(fmaxf(r1, 0.f), 6.f);
    float* dst = g_kv + (size_t)n * KV_N + m * E_DIM;
    dst[e0] = r0;
    dst[e1] = r1;
}

// ================= Kernel 2: persistent double-buffered attention ==============
#define TILE_P  56
#define NTH     896                       // 28 warps
#define NTILES  ((HW / TILE_P) * N_B)     // 1792

// xs buffer: [q 0..7][c' 0..47][px 0..55 +4 pad] -> q*2884 + c'*60 + px
#define QSTR   2884
#define XBUF   (8 * QSTR)                 // 23072 words
#define KROW   416                        // Ks: [k][q*52 + c']
#define VROW   388                        // Vs: [k][c] padded row
#define OFF_XS0  0
#define OFF_XS1  23072
#define OFF_KS   46144
#define OFF_VS   (OFF_KS + 8 * KROW)      // 49472
#define OFF_SC   (OFF_VS + 8 * VROW)      // 52576
#define OFF_AT   (OFF_SC + TILE_P * 8)    // 53024
#define SM_WORDS (OFF_AT + TILE_P * 8)    // 53472
#define SM_BYTES (SM_WORDS * 4)           // 213888

__device__ __forceinline__ void issue_tile_loads(
    const float* __restrict__ x, int t, float* buf, int tid)
{
    const int n  = t / 56;
    const int p0 = (t - n * 56) * TILE_P;
    const float* xb = x + (size_t)n * C_DIM * HW + p0;
    #pragma unroll
    for (int tt = 0; tt < 6; tt++) {
        int i  = tid + tt * NTH;          // float4 index, 0..5375
        int c  = i / 14;
        int j  = i - c * 14;
        int q  = c / 48;
        int cp = c - q * 48;
        uint32_t dst = (uint32_t)__cvta_generic_to_shared(buf + q * QSTR + cp * 60 + j * 4);
        const float* src = xb + (size_t)c * HW + j * 4;
        asm volatile("cp.async.cg.shared.global [%0], [%1], 16;\n" :: "r"(dst), "l"(src));
    }
    asm volatile("cp.async.commit_group;\n");
}

__device__ __forceinline__ void stage_kv(int n, float* Ks, float* Vs, int tid)
{
    const float4* kv4 = (const float4*)g_kv + (size_t)n * (KV_N / 4);
    for (int i = tid; i < KV_N / 4; i += NTH) {
        float4 o = kv4[i];
        int m = i / 192;
        int j = i - m * 192;
        int e = j * 4;
        if (e < C_DIM) {
            int q = e / 48, cp = e - q * 48;
            *(float4*)&Ks[m * KROW + q * 52 + cp] = o;
        } else {
            *(float4*)&Vs[m * VROW + (e - C_DIM)] = o;
        }
    }
}

__global__ __launch_bounds__(NTH, 1) void attn_persist(
    const float* __restrict__ x,
    float* __restrict__ out)
{
    extern __shared__ float sm[];
    float* xsb[2] = { sm + OFF_XS0, sm + OFF_XS1 };
    float* Ks     = sm + OFF_KS;
    float* Vs     = sm + OFF_VS;
    float* scores = sm + OFF_SC;
    float* attnw  = sm + OFF_AT;

    const int tid = threadIdx.x;
    const int G   = gridDim.x;
    const int cta = blockIdx.x;

    const int T = NTILES / G;
    const int R = NTILES % G;
    const int t0  = cta * T + (cta < R ? cta : R);
    const int cnt = T + (cta < R ? 1 : 0);
    if (cnt == 0) return;

    int curn = -1;

    issue_tile_loads(x, t0, xsb[0], tid);

    for (int j = 0; j < cnt; j++) {
        const int t  = t0 + j;
        const int n  = t / 56;
        const int p0 = (t - n * 56) * TILE_P;
        float* buf = xsb[j & 1];

        if (j + 1 < cnt) {
            issue_tile_loads(x, t + 1, xsb[(j + 1) & 1], tid);
            asm volatile("cp.async.wait_group 1;\n");
        } else {
            asm volatile("cp.async.wait_group 0;\n");
        }

        if (n != curn) {
            stage_kv(n, Ks, Vs, tid);
            curn = n;
        }
        __syncthreads();              // buf + KV ready

        // ---------- phase 1: scores (1 k per thread, 4 px per warp) ----------
        {
            const int w     = tid >> 5;
            const int lane  = tid & 31;
            const int khalf = w / 14;          // 0..1
            const int pg    = w - khalf * 14;  // 0..13
            const int kg    = lane >> 3;       // 0..3
            const int q     = lane & 7;        // 0..7
            const int k     = khalf * 4 + kg;
            const float* Kq = Ks + k * KROW + q * 52;
            const float* xq = buf + q * QSTR + pg * 4;

            float acc[4] = {0.f, 0.f, 0.f, 0.f};
            #pragma unroll 4
            for (int i4 = 0; i4 < 12; i4++) {
                float4 kk = *(const float4*)(Kq + i4 * 4);
                float kv[4] = {kk.x, kk.y, kk.z, kk.w};
                #pragma unroll
                for (int cc = 0; cc < 4; cc++) {
                    float4 xv = *(const float4*)(xq + (i4 * 4 + cc) * 60);
                    acc[0] += xv.x * kv[cc]; acc[1] += xv.y * kv[cc];
                    acc[2] += xv.z * kv[cc]; acc[3] += xv.w * kv[cc];
                }
            }
            // reduce over q (octet butterfly)
            #pragma unroll
            for (int off = 1; off < 8; off <<= 1) {
                #pragma unroll
                for (int pp = 0; pp < 4; pp++)
                    acc[pp] += __shfl_xor_sync(0xffffffffu, acc[pp], off);
            }
            if (q == 0) {
                #pragma unroll
                for (int pp = 0; pp < 4; pp++)
                    scores[(pg * 4 + pp) * 8 + k] = acc[pp];
            }
        }
        __syncthreads();

        // ---------- softmax over k=8 ----------
        if (tid < TILE_P) {
            float4 u0 = *(const float4*)&scores[tid * 8];
            float4 u1 = *(const float4*)&scores[tid * 8 + 4];
            float s[8] = {u0.x, u0.y, u0.z, u0.w, u1.x, u1.y, u1.z, u1.w};
            float mx = s[0];
            #pragma unroll
            for (int k = 1; k < 8; k++) mx = fmaxf(mx, s[k]);
            float sum = 0.f;
            #pragma unroll
            for (int k = 0; k < 8; k++) { s[k] = __expf(s[k] - mx); sum += s[k]; }
            float inv = 1.0f / sum;
            *(float4*)&attnw[tid * 8]     = make_float4(s[0]*inv, s[1]*inv, s[2]*inv, s[3]*inv);
            *(float4*)&attnw[tid * 8 + 4] = make_float4(s[4]*inv, s[5]*inv, s[6]*inv, s[7]*inv);
        }
        __syncthreads();

        // ---------- phase 2: out = x + attn @ V ----------
        {
            const int cg  = tid / 14;          // 0..63 -> 6 channels
            const int pg2 = tid - cg * 14;     // 0..13 -> 4 pixels

            float a[4][8];
            #pragma unroll
            for (int pp = 0; pp < 4; pp++) {
                float4 u0 = *(const float4*)&attnw[(pg2 * 4 + pp) * 8];
                float4 u1 = *(const float4*)&attnw[(pg2 * 4 + pp) * 8 + 4];
                a[pp][0] = u0.x; a[pp][1] = u0.y; a[pp][2] = u0.z; a[pp][3] = u0.w;
                a[pp][4] = u1.x; a[pp][5] = u1.y; a[pp][6] = u1.z; a[pp][7] = u1.w;
            }

            float* op = out + (size_t)n * C_DIM * HW + p0 + pg2 * 4;
            #pragma unroll 3
            for (int jj = 0; jj < 6; jj++) {
                int c  = cg * 6 + jj;
                int q  = c / 48;
                int cp = c - q * 48;
                float4 xv = *(const float4*)(buf + q * QSTR + cp * 60 + pg2 * 4);
                float o0 = xv.x, o1 = xv.y, o2 = xv.z, o3 = xv.w;
                const float* Vc = Vs + c;
                #pragma unroll
                for (int k = 0; k < 8; k++) {
                    float vk = Vc[k * VROW];
                    o0 += a[0][k] * vk; o1 += a[1][k] * vk;
                    o2 += a[2][k] * vk; o3 += a[3][k] * vk;
                }
                *(float4*)(op + (size_t)c * HW) = make_float4(o0, o1, o2, o3);
            }
        }
        __syncthreads();   // all reads of buf done before it is overwritten
    }
}

// ================= launch ======================================================
extern "C" void kernel_launch(void* const* d_in, const int* in_sizes, int n_in,
                              void* d_out, int out_size)
{
    const float* x  = (const float*)d_in[0];
    const float* gf = (const float*)d_in[1];
    const float* W  = (const float*)d_in[2];
    const float* b  = (const float*)d_in[3];
    float* out = (float*)d_out;

    kv_kernel<<<dim3(E_DIM / 64, N_B), 256>>>(gf, W, b);

    int nsm = 0;
    cudaDeviceGetAttribute(&nsm, cudaDevAttrMultiProcessorCount, 0);
    if (nsm <= 0) nsm = 148;
    if (nsm > NTILES) nsm = NTILES;

    cudaFuncSetAttribute(attn_persist, cudaFuncAttributeMaxDynamicSharedMemorySize, SM_BYTES);
    attn_persist<<<nsm, NTH, SM_BYTES>>>(x, out);
}

// round 8
// speedup vs baseline: 2.2596x; 2.2596x over previous
#include <cuda_runtime.h>
#include <math.h>
#include <stdint.h>

// Problem constants
#define N_B     32
#define C_DIM   384
#define HW      3136        // 56*56
#define M_DIM   8
#define D_MODEL 768
#define E_DIM   768         // 2*C
#define KV_N    (M_DIM * E_DIM)   // 6144 per batch

// ---------------- device scratch -----------------------------------------------
#define NSPLIT 8
__device__ __align__(16) float g_kvp[NSPLIT * N_B * KV_N]; // raw GEMM partials

// ================= Kernel 1: split-K GEMM partials (measured ~19us) ============
#define BM 32
#define BN 64
#define BK 32
#define DSPL (D_MODEL / NSPLIT)   // 96

__global__ __launch_bounds__(256) void kvp_kernel(
    const float* __restrict__ gf,
    const float* __restrict__ W)
{
    __shared__ float As[BK][BM + 2];
    __shared__ float Bs[BK][BN + 4];

    const int tid = threadIdx.x;
    const int tx  = tid & 15;
    const int ty  = tid >> 4;
    const int eb  = blockIdx.x * BN;
    const int rb  = blockIdx.y * BM;
    const int s   = blockIdx.z;

    float acc[2][4];
    #pragma unroll
    for (int i = 0; i < 2; i++)
        #pragma unroll
        for (int j = 0; j < 4; j++) acc[i][j] = 0.f;

    for (int kb = s * DSPL; kb < (s + 1) * DSPL; kb += BK) {
        #pragma unroll
        for (int i = 0; i < 4; i++) {
            int idx = tid + i * 256;
            int r  = idx >> 5;
            int kk = idx & 31;
            As[kk][r] = gf[(size_t)(rb + r) * D_MODEL + kb + kk];
        }
        #pragma unroll
        for (int i = 0; i < 8; i++) {
            int idx = tid + i * 256;
            int e  = idx >> 5;
            int kk = idx & 31;
            Bs[kk][e] = W[(size_t)(eb + e) * D_MODEL + kb + kk];
        }
        __syncthreads();

        #pragma unroll
        for (int kk = 0; kk < BK; kk++) {
            float2 av = *(const float2*)&As[kk][ty * 2];
            float4 bv = *(const float4*)&Bs[kk][tx * 4];
            acc[0][0] += av.x * bv.x; acc[0][1] += av.x * bv.y;
            acc[0][2] += av.x * bv.z; acc[0][3] += av.x * bv.w;
            acc[1][0] += av.y * bv.x; acc[1][1] += av.y * bv.y;
            acc[1][2] += av.y * bv.z; acc[1][3] += av.y * bv.w;
        }
        __syncthreads();
    }

    float* dst = g_kvp + (size_t)s * (N_B * KV_N);
    #pragma unroll
    for (int r = 0; r < 2; r++) {
        float4 o = make_float4(acc[r][0], acc[r][1], acc[r][2], acc[r][3]);
        *(float4*)&dst[(size_t)(rb + ty * 2 + r) * E_DIM + eb + tx * 4] = o;
    }
}

// ================= Kernel 2: persistent attention, 2 CTAs/SM ====================
#define TILE_P   28
#define NTH      224                       // 7 warps
#define TPB      (HW / TILE_P)             // 112 tiles per batch
#define NTILES   (TPB * N_B)               // 3584

// xs buffer: [q 0..7][c' 0..47][px 0..27] ; QSTR=1348 -> q-chunks at 17q mod 32
#define QSTR     1348
#define XBUF     (8 * QSTR)                // 10784 words (43.1 KB)
#define KROW     432                       // (24kg+13q) mod 32 distinct -> no conflicts
#define OFF_XS0  0
#define OFF_XS1  10784
#define OFF_KS   21568
#define OFF_VS   (OFF_KS + 8 * KROW)       // 25024 ; V: [k][c] rows of 384
#define OFF_AT   (OFF_VS + 8 * 384)        // 28096
#define SM_WORDS (OFF_AT + TILE_P * 8)     // 28320
#define SM_BYTES (SM_WORDS * 4)            // 113280 -> 2 CTAs/SM

__device__ __forceinline__ void issue_tile_loads(
    const float* __restrict__ x, int t, float* buf, int tid)
{
    const int n  = t / TPB;
    const int p0 = (t - n * TPB) * TILE_P;
    const float* xb = x + (size_t)n * C_DIM * HW + p0;
    #pragma unroll
    for (int tt = 0; tt < 12; tt++) {              // 2688 float4 / 224 thr
        int i  = tid + tt * NTH;
        int c  = i / 7;                            // 7 float4 per channel row
        int j  = i - c * 7;
        int q  = c / 48;
        int cp = c - q * 48;
        uint32_t dst = (uint32_t)__cvta_generic_to_shared(buf + q * QSTR + cp * TILE_P + j * 4);
        const float* src = xb + (size_t)c * HW + j * 4;
        asm volatile("cp.async.cg.shared.global [%0], [%1], 16;\n" :: "r"(dst), "l"(src));
    }
    asm volatile("cp.async.commit_group;\n");
}

__device__ __forceinline__ void stage_kv(
    int n, const float* __restrict__ bias, float* Ks, float* Vs, int tid)
{
    const float4* pp = (const float4*)g_kvp;
    const float4* b4 = (const float4*)bias;
    const int base = n * (KV_N / 4);
    for (int i = tid; i < KV_N / 4; i += NTH) {    // 1536 float4
        float4 s0 = pp[0 * 49152 + base + i];
        float4 s1 = pp[1 * 49152 + base + i];
        float4 s2 = pp[2 * 49152 + base + i];
        float4 s3 = pp[3 * 49152 + base + i];
        float4 s4 = pp[4 * 49152 + base + i];
        float4 s5 = pp[5 * 49152 + base + i];
        float4 s6 = pp[6 * 49152 + base + i];
        float4 s7 = pp[7 * 49152 + base + i];
        int m = i / 192;
        int j = i - m * 192;
        float4 bb = b4[j];
        float4 o;
        o.x = fminf(fmaxf(s0.x+s1.x+s2.x+s3.x+s4.x+s5.x+s6.x+s7.x + bb.x, 0.f), 6.f);
        o.y = fminf(fmaxf(s0.y+s1.y+s2.y+s3.y+s4.y+s5.y+s6.y+s7.y + bb.y, 0.f), 6.f);
        o.z = fminf(fmaxf(s0.z+s1.z+s2.z+s3.z+s4.z+s5.z+s6.z+s7.z + bb.z, 0.f), 6.f);
        o.w = fminf(fmaxf(s0.w+s1.w+s2.w+s3.w+s4.w+s5.w+s6.w+s7.w + bb.w, 0.f), 6.f);
        int e = j * 4;
        if (e < C_DIM) {
            int q = e / 48, cp = e - q * 48;
            *(float4*)&Ks[m * KROW + q * 52 + cp] = o;
        } else {
            *(float4*)&Vs[m * 384 + (e - C_DIM)] = o;
        }
    }
}

__global__ __launch_bounds__(NTH, 2) void attn_persist(
    const float* __restrict__ x,
    const float* __restrict__ bias,
    float* __restrict__ out)
{
    extern __shared__ float sm[];
    float* xsb[2] = { sm + OFF_XS0, sm + OFF_XS1 };
    float* Ks     = sm + OFF_KS;
    float* Vs     = sm + OFF_VS;
    float* attnw  = sm + OFF_AT;

    const int tid = threadIdx.x;
    const int G   = gridDim.x;
    const int cta = blockIdx.x;

    const int T = NTILES / G;
    const int R = NTILES % G;
    const int t0  = cta * T + (cta < R ? cta : R);
    const int cnt = T + (cta < R ? 1 : 0);
    if (cnt == 0) return;

    int curn = -1;

    issue_tile_loads(x, t0, xsb[0], tid);

    for (int j = 0; j < cnt; j++) {
        const int t  = t0 + j;
        const int n  = t / TPB;
        const int p0 = (t - n * TPB) * TILE_P;
        float* buf = xsb[j & 1];

        if (j + 1 < cnt) {
            issue_tile_loads(x, t + 1, xsb[(j + 1) & 1], tid);
            asm volatile("cp.async.wait_group 1;\n");
        } else {
            asm volatile("cp.async.wait_group 0;\n");
        }

        if (n != curn) {
            stage_kv(n, bias, Ks, Vs, tid);
            curn = n;
        }
        __syncthreads();               // (1) buf + KV ready

        // ---------- phase 1: scores + fused softmax ----------
        {
            const int pg   = tid >> 5;       // warp id 0..6 -> 4 pixels
            const int lane = tid & 31;
            const int kg   = lane >> 3;      // 0..3 -> k pair {2kg, 2kg+1}
            const int q    = lane & 7;       // 0..7 -> 48-channel block
            const float* Kq0 = Ks + (2 * kg) * KROW + q * 52;
            const float* Kq1 = Kq0 + KROW;
            const float* xq  = buf + q * QSTR + pg * 4;

            float acc0[4] = {0.f, 0.f, 0.f, 0.f};
            float acc1[4] = {0.f, 0.f, 0.f, 0.f};

            #pragma unroll 4
            for (int i4 = 0; i4 < 12; i4++) {
                float4 k0 = *(const float4*)(Kq0 + i4 * 4);
                float4 k1 = *(const float4*)(Kq1 + i4 * 4);
                float k0v[4] = {k0.x, k0.y, k0.z, k0.w};
                float k1v[4] = {k1.x, k1.y, k1.z, k1.w};
                #pragma unroll
                for (int cc = 0; cc < 4; cc++) {
                    float4 xv = *(const float4*)(xq + (i4 * 4 + cc) * TILE_P);
                    acc0[0] += xv.x * k0v[cc]; acc0[1] += xv.y * k0v[cc];
                    acc0[2] += xv.z * k0v[cc]; acc0[3] += xv.w * k0v[cc];
                    acc1[0] += xv.x * k1v[cc]; acc1[1] += xv.y * k1v[cc];
                    acc1[2] += xv.z * k1v[cc]; acc1[3] += xv.w * k1v[cc];
                }
            }
            // reduce over q (octet butterfly)
            #pragma unroll
            for (int off = 1; off < 8; off <<= 1) {
                #pragma unroll
                for (int pp = 0; pp < 4; pp++) {
                    acc0[pp] += __shfl_xor_sync(0xffffffffu, acc0[pp], off);
                    acc1[pp] += __shfl_xor_sync(0xffffffffu, acc1[pp], off);
                }
            }
            // each lane picks one pixel (px = q&3), then kg-exchange for all 8 k
            const int sel = q & 3;
            float s0 = sel == 0 ? acc0[0] : sel == 1 ? acc0[1] : sel == 2 ? acc0[2] : acc0[3];
            float s1 = sel == 0 ? acc1[0] : sel == 1 ? acc1[1] : sel == 2 ? acc1[2] : acc1[3];

            float o0 = __shfl_xor_sync(0xffffffffu, s0, 8);
            float o1 = __shfl_xor_sync(0xffffffffu, s1, 8);
            float t0v, t1v, t2v, t3v;                 // k-quad for base (kg>>1)*4
            if ((kg & 1) == 0) { t0v = s0; t1v = s1; t2v = o0; t3v = o1; }
            else               { t0v = o0; t1v = o1; t2v = s0; t3v = s1; }
            float r0 = __shfl_xor_sync(0xffffffffu, t0v, 16);
            float r1 = __shfl_xor_sync(0xffffffffu, t1v, 16);
            float r2 = __shfl_xor_sync(0xffffffffu, t2v, 16);
            float r3 = __shfl_xor_sync(0xffffffffu, t3v, 16);
            float sc[8];
            if (kg < 2) { sc[0]=t0v; sc[1]=t1v; sc[2]=t2v; sc[3]=t3v; sc[4]=r0; sc[5]=r1; sc[6]=r2; sc[7]=r3; }
            else        { sc[0]=r0;  sc[1]=r1;  sc[2]=r2;  sc[3]=r3;  sc[4]=t0v; sc[5]=t1v; sc[6]=t2v; sc[7]=t3v; }

            // softmax over k=8 (all lanes; only kg==0 && q<4 write)
            float mx = sc[0];
            #pragma unroll
            for (int k = 1; k < 8; k++) mx = fmaxf(mx, sc[k]);
            float sum = 0.f;
            #pragma unroll
            for (int k = 0; k < 8; k++) { sc[k] = __expf(sc[k] - mx); sum += sc[k]; }
            float inv = 1.0f / sum;
            if (kg == 0 && q < 4) {
                float* ap = &attnw[(pg * 4 + q) * 8];
                *(float4*)(ap)     = make_float4(sc[0]*inv, sc[1]*inv, sc[2]*inv, sc[3]*inv);
                *(float4*)(ap + 4) = make_float4(sc[4]*inv, sc[5]*inv, sc[6]*inv, sc[7]*inv);
            }
        }
        __syncthreads();               // (2) attnw ready

        // ---------- phase 2: out = x + attn @ V ----------
        {
            const int cg  = tid / 7;           // 0..31 -> 12 channels
            const int pg2 = tid - cg * 7;      // 0..6  -> 4 pixels

            float a[4][8];
            #pragma unroll
            for (int pp = 0; pp < 4; pp++) {
                float4 u0 = *(const float4*)&attnw[(pg2 * 4 + pp) * 8];
                float4 u1 = *(const float4*)&attnw[(pg2 * 4 + pp) * 8 + 4];
                a[pp][0] = u0.x; a[pp][1] = u0.y; a[pp][2] = u0.z; a[pp][3] = u0.w;
                a[pp][4] = u1.x; a[pp][5] = u1.y; a[pp][6] = u1.z; a[pp][7] = u1.w;
            }

            float* op = out + (size_t)n * C_DIM * HW + p0 + pg2 * 4;
            #pragma unroll 4
            for (int jj = 0; jj < 12; jj++) {
                int c  = cg * 12 + jj;
                int q  = c / 48;
                int cp = c - q * 48;
                float4 xv = *(const float4*)(buf + q * QSTR + cp * TILE_P + pg2 * 4);
                float v0 = xv.x, v1 = xv.y, v2 = xv.z, v3 = xv.w;
                const float* Vc = Vs + c;
                #pragma unroll
                for (int k = 0; k < 8; k++) {
                    float vk = Vc[k * 384];
                    v0 += a[0][k] * vk; v1 += a[1][k] * vk;
                    v2 += a[2][k] * vk; v3 += a[3][k] * vk;
                }
                *(float4*)(op + (size_t)c * HW) = make_float4(v0, v1, v2, v3);
            }
        }
        __syncthreads();               // (3) buf reads done before next overwrite
    }
}

// ================= launch ======================================================
extern "C" void kernel_launch(void* const* d_in, const int* in_sizes, int n_in,
                              void* d_out, int out_size)
{
    const float* x  = (const float*)d_in[0];
    const float* gf = (const float*)d_in[1];
    const float* W  = (const float*)d_in[2];
    const float* b  = (const float*)d_in[3];
    float* out = (float*)d_out;

    kvp_kernel<<<dim3(E_DIM / BN, (N_B * M_DIM) / BM, NSPLIT), 256>>>(gf, W);

    int nsm = 0;
    cudaDeviceGetAttribute(&nsm, cudaDevAttrMultiProcessorCount, 0);
    if (nsm <= 0) nsm = 148;
    int grid = 2 * nsm;
    if (grid > NTILES) grid = NTILES;

    cudaFuncSetAttribute(attn_persist, cudaFuncAttributeMaxDynamicSharedMemorySize, SM_BYTES);
    attn_persist<<<grid, NTH, SM_BYTES>>>(x, b, out);
}